// round 1
// baseline (speedup 1.0000x reference)
#include <cuda_runtime.h>
#include <math.h>

// Layout / problem constants
#define NIMG 256        // B*N = 64*4
#define IMGPIX 4096     // 64*64 crop

// scratch: per-image masked/scaled crop, summed over n in kernel 2
__device__ float g_tmp[NIMG * IMGPIX];

// dynamic shared layout (bytes):
//  Cs   : 64*64 float2  = 32768
//  Gs   : 48*256 float2 = 98304
//  Wt   : 256 float2    = 2048
//  crop : 4096 float    = 16384
//  red  : 32 float      = 128
#define SM_CS   0
#define SM_GS   (32768)
#define SM_WT   (32768 + 98304)
#define SM_CROP (32768 + 98304 + 2048)
#define SM_RED  (32768 + 98304 + 2048 + 16384)
#define SM_TOTAL (32768 + 98304 + 2048 + 16384 + 128)

extern __shared__ char smem_raw[];

__global__ void __launch_bounds__(1024, 1)
render_kernel(const float* __restrict__ X,  const float* __restrict__ Y,
              const float* __restrict__ Z,  const float* __restrict__ Aa,
              const float* __restrict__ Bg, const float* __restrict__ P,
              const float* __restrict__ phase0)
{
    float2* Cs   = (float2*)(smem_raw + SM_CS);    // [64][64]
    float2* Gs   = (float2*)(smem_raw + SM_GS);    // [48][256]
    float2* Wt   = (float2*)(smem_raw + SM_WT);    // [256]
    float*  crop = (float*) (smem_raw + SM_CROP);  // [64][64]
    float*  red  = (float*) (smem_raw + SM_RED);   // [32]

    const int img  = blockIdx.x;
    const int tid  = threadIdx.x;
    const int lane = tid & 31;
    const int warp = tid >> 5;

    const float x = X[img], y = Y[img], z = Z[img];

    // ---- twiddle table: W[k] = exp(2*pi*i*k/256) ----
    if (tid < 256) {
        float s, c;
        sincospif((float)tid * (1.0f / 128.0f), &s, &c);
        Wt[tid] = make_float2(c, s);
    }

    // ---- Phase A: pupil C[a][b] = mag * exp(i*psi) (64x64, only disk nonzero)
    const float k2pi = 6.283185307179586f / 256.0f;
    #pragma unroll
    for (int k = 0; k < 4; k++) {
        int idx = tid + k * 1024;
        int a = idx >> 6, b = idx & 63;
        float us = (-1.0f + (float)a * (2.0f / 63.0f)) * (1.0f / 0.75f);
        float vs = (-1.0f + (float)b * (2.0f / 63.0f)) * (1.0f / 0.75f);
        float R = sqrtf(us * us + vs * vs);
        float2 c2 = make_float2(0.0f, 0.0f);
        if (R <= 1.0f) {
            float prop = sqrtf(fmaxf(1.0f - R * R, 0.0f));
            float psi = phase0[idx] + prop * z
                        - k2pi * ((float)(a - 32) * x + (float)(b - 32) * y);
            float sn, cs;
            sincosf(psi, &sn, &cs);
            c2 = make_float2(cs, sn);
        }
        Cs[idx] = c2;
    }
    __syncthreads();

    // ---- Phase B: G[ar][v] = sum_b C[ar+8][b] * W[(b-32)*v], b in [8,56)
    // rotation recurrence: w_{b+1} = w_b * exp(2*pi*i*v/256)
    for (int i = 0; i < 12; i++) {
        int tau = warp + 32 * i;          // 0..383
        int ar  = tau >> 3;               // 0..47
        int a   = ar + 8;
        int v   = ((tau & 7) << 5) + lane;

        float2 w   = Wt[(-24 * v) & 255]; // b=8 -> (b-32) = -24
        float2 rot = Wt[v];
        float gr = 0.0f, gi = 0.0f;
        const float2* Crow = Cs + (a << 6);
        #pragma unroll 8
        for (int b = 8; b < 56; b++) {
            float2 c = Crow[b];
            gr = fmaf(c.x, w.x, fmaf(-c.y, w.y, gr));
            gi = fmaf(c.x, w.y, fmaf( c.y, w.x, gi));
            float nwr = fmaf(w.x, rot.x, -(w.y * rot.y));
            float nwi = fmaf(w.x, rot.y,  (w.y * rot.x));
            w.x = nwr; w.y = nwi;
        }
        Gs[(ar << 8) + v] = make_float2(gr, gi);
    }
    __syncthreads();

    // ---- Phase C: field[u][v] = sum_ar G[ar][v] * W[(ar+8-32)*u], full 256x256
    // warp: fixed u-tile of 4, lanes over v. Track global max; stash crop.
    float lmax = 0.0f;
    for (int i = 0; i < 16; i++) {
        int tau  = warp + 32 * i;         // 0..511
        int ut   = tau >> 3;              // 0..63
        int vblk = tau & 7;
        int v    = (vblk << 5) + lane;
        int u0   = ut << 2;

        float a0r = 0.f, a0i = 0.f, a1r = 0.f, a1i = 0.f;
        float a2r = 0.f, a2i = 0.f, a3r = 0.f, a3i = 0.f;
        int i0 = (-24 * (u0    )) & 255;
        int i1 = (-24 * (u0 + 1)) & 255;
        int i2 = (-24 * (u0 + 2)) & 255;
        int i3 = (-24 * (u0 + 3)) & 255;

        const float2* Gcol = Gs + v;
        #pragma unroll 4
        for (int ar = 0; ar < 48; ar++) {
            float2 g  = Gcol[ar << 8];
            float2 w0 = Wt[i0 & 255];
            float2 w1 = Wt[i1 & 255];
            float2 w2 = Wt[i2 & 255];
            float2 w3 = Wt[i3 & 255];
            a0r = fmaf(g.x, w0.x, fmaf(-g.y, w0.y, a0r));
            a0i = fmaf(g.x, w0.y, fmaf( g.y, w0.x, a0i));
            a1r = fmaf(g.x, w1.x, fmaf(-g.y, w1.y, a1r));
            a1i = fmaf(g.x, w1.y, fmaf( g.y, w1.x, a1i));
            a2r = fmaf(g.x, w2.x, fmaf(-g.y, w2.y, a2r));
            a2i = fmaf(g.x, w2.y, fmaf( g.y, w2.x, a2i));
            a3r = fmaf(g.x, w3.x, fmaf(-g.y, w3.y, a3r));
            a3i = fmaf(g.x, w3.y, fmaf( g.y, w3.x, a3i));
            i0 += u0; i1 += u0 + 1; i2 += u0 + 2; i3 += u0 + 3;
        }

        int t = (v + 32) & 255;           // crop column (valid if < 64)
        float p2;
        int s;
        p2 = fmaf(a0r, a0r, a0i * a0i); lmax = fmaxf(lmax, p2);
        s = (u0 + 0 + 32) & 255; if (s < 64 && t < 64) crop[(s << 6) + t] = p2;
        p2 = fmaf(a1r, a1r, a1i * a1i); lmax = fmaxf(lmax, p2);
        s = (u0 + 1 + 32) & 255; if (s < 64 && t < 64) crop[(s << 6) + t] = p2;
        p2 = fmaf(a2r, a2r, a2i * a2i); lmax = fmaxf(lmax, p2);
        s = (u0 + 2 + 32) & 255; if (s < 64 && t < 64) crop[(s << 6) + t] = p2;
        p2 = fmaf(a3r, a3r, a3i * a3i); lmax = fmaxf(lmax, p2);
        s = (u0 + 3 + 32) & 255; if (s < 64 && t < 64) crop[(s << 6) + t] = p2;
    }

    // ---- CTA max reduction ----
    #pragma unroll
    for (int o = 16; o > 0; o >>= 1)
        lmax = fmaxf(lmax, __shfl_xor_sync(0xFFFFFFFFu, lmax, o));
    if (lane == 0) red[warp] = lmax;
    __syncthreads();
    if (warp == 0) {
        float m = red[lane];
        #pragma unroll
        for (int o = 16; o > 0; o >>= 1)
            m = fmaxf(m, __shfl_xor_sync(0xFFFFFFFFu, m, o));
        if (lane == 0) red[0] = m;
    }
    __syncthreads();
    const float maxv = red[0];

    // ---- epilogue: img = (psf/max * A + bg) * (p > 0.5) -> g_tmp ----
    const float A    = Aa[img];
    const float bg   = Bg[img];
    const float mask = (P[img] > 0.5f) ? 1.0f : 0.0f;
    const float scale = (A / maxv) * mask;
    const float bgm   = bg * mask;
    #pragma unroll
    for (int k = 0; k < 4; k++) {
        int idx = tid + k * 1024;
        g_tmp[img * IMGPIX + idx] = fmaf(crop[idx], scale, bgm);
    }
}

__global__ void sum_kernel(float* __restrict__ out)
{
    int j = blockIdx.x * blockDim.x + threadIdx.x;
    if (j < 64 * IMGPIX) {
        int b = j >> 12, pix = j & 4095;
        const float* t = g_tmp + (size_t)(b * 4) * IMGPIX + pix;
        out[j] = (t[0] + t[IMGPIX]) + (t[2 * IMGPIX] + t[3 * IMGPIX]);
    }
}

extern "C" void kernel_launch(void* const* d_in, const int* in_sizes, int n_in,
                              void* d_out, int out_size)
{
    (void)in_sizes; (void)n_in; (void)out_size;
    cudaFuncSetAttribute(render_kernel,
                         cudaFuncAttributeMaxDynamicSharedMemorySize, SM_TOTAL);
    render_kernel<<<NIMG, 1024, SM_TOTAL>>>(
        (const float*)d_in[0], (const float*)d_in[1], (const float*)d_in[2],
        (const float*)d_in[3], (const float*)d_in[4], (const float*)d_in[5],
        (const float*)d_in[6]);
    sum_kernel<<<(64 * IMGPIX + 1023) / 1024, 1024>>>((float*)d_out);
}

// round 2
// speedup vs baseline: 2.7054x; 2.7054x over previous
#include <cuda_runtime.h>
#include <math.h>

#define NIMG 256        // B*N = 64*4
#define IMGPIX 4096     // 64*64 crop

__device__ float g_tmp[NIMG * IMGPIX];

// ---- dynamic shared layout (bytes) ----
#define SM_CS   0                    // float2 [64][64]   = 32768
#define SM_SDB  (SM_CS + 32768)      // float4 [49][24]   = 18816
#define SM_WT   (SM_SDB + 18816)     // float2 [256]      = 2048
#define SM_WP   (SM_WT + 2048)       // ulonglong2 [256]  = 4096
#define SM_SG   (SM_WP + 4096)       // float2 [24][256]  = 49152
#define SM_DG   (SM_SG + 49152)      // float2 [24][256]  = 49152
#define SM_G0   (SM_DG + 49152)      // float2 [256]      = 2048
#define SM_CROP (SM_G0 + 2048)       // float  [4096]     = 16384
#define SM_RED  (SM_CROP + 16384)    // float  [32]       = 128
#define SM_TOTAL (SM_RED + 128)      // 174592 bytes

extern __shared__ char smem_raw[];

#define FMA2(d, a, b, c) \
    asm("fma.rn.f32x2 %0, %1, %2, %3;" : "=l"(d) : "l"(a), "l"(b), "l"(c))

__device__ __forceinline__ float2 u2f2(unsigned long long v) {
    float2 r;
    asm("mov.b64 {%0, %1}, %2;" : "=f"(r.x), "=f"(r.y) : "l"(v));
    return r;
}

__global__ void __launch_bounds__(1024, 1)
render_kernel(const float* __restrict__ X,  const float* __restrict__ Y,
              const float* __restrict__ Z,  const float* __restrict__ Aa,
              const float* __restrict__ Bg, const float* __restrict__ P,
              const float* __restrict__ phase0)
{
    float2*     Cs   = (float2*)    (smem_raw + SM_CS);
    float4*     SDB  = (float4*)    (smem_raw + SM_SDB);
    float2*     Wt   = (float2*)    (smem_raw + SM_WT);
    ulonglong2* Wp   = (ulonglong2*)(smem_raw + SM_WP);
    float2*     SG   = (float2*)    (smem_raw + SM_SG);
    float2*     DG   = (float2*)    (smem_raw + SM_DG);
    float2*     G0   = (float2*)    (smem_raw + SM_G0);
    float*      crop = (float*)     (smem_raw + SM_CROP);
    float*      red  = (float*)     (smem_raw + SM_RED);

    const int img  = blockIdx.x;
    const int tid  = threadIdx.x;
    const int lane = tid & 31;
    const int warp = tid >> 5;

    const float x = X[img], y = Y[img], z = Z[img];

    // ---- twiddle tables: W[k] = exp(2*pi*i*k/256) ----
    if (tid < 256) {
        float s, c;
        sincospif((float)tid * (1.0f / 128.0f), &s, &c);
        Wt[tid] = make_float2(c, s);
        unsigned long long cc, ss;
        asm("mov.b64 %0, {%1, %1};" : "=l"(cc) : "f"(c));
        asm("mov.b64 %0, {%1, %1};" : "=l"(ss) : "f"(s));
        Wp[tid] = make_ulonglong2(cc, ss);
    }

    // ---- Phase A: pupil C[a][b] (64x64, zero outside disk) ----
    const float k2pi = 6.283185307179586f / 256.0f;
    #pragma unroll
    for (int k = 0; k < 4; k++) {
        int idx = tid + k * 1024;
        int a = idx >> 6, b = idx & 63;
        float us = (-1.0f + (float)a * (2.0f / 63.0f)) * (1.0f / 0.75f);
        float vs = (-1.0f + (float)b * (2.0f / 63.0f)) * (1.0f / 0.75f);
        float R = sqrtf(us * us + vs * vs);
        float2 c2 = make_float2(0.0f, 0.0f);
        if (R <= 1.0f) {
            float prop = sqrtf(fmaxf(1.0f - R * R, 0.0f));
            float psi = phase0[idx] + prop * z
                        - k2pi * ((float)(a - 32) * x + (float)(b - 32) * y);
            float sn, cs;
            sincosf(psi, &sn, &cs);
            c2 = make_float2(cs, sn);
        }
        Cs[idx] = c2;
    }
    __syncthreads();

    // ---- SDB: per-row b-fold sums. SDB[r][mb-1] = (S.r,S.i,D.i,D.r)
    // S = C[a][32+mb]+C[a][32-mb], D = C[a][32+mb]-C[a][32-mb], a=r+8
    for (int idx = tid; idx < 49 * 24; idx += 1024) {
        int r  = idx / 24;
        int mb = idx - r * 24 + 1;          // 1..24
        int a  = r + 8;
        float2 cu = Cs[a * 64 + 32 + mb];
        float2 cd = Cs[a * 64 + 32 - mb];
        SDB[idx] = make_float4(cu.x + cd.x, cu.y + cd.y,
                               cu.y - cd.y, cu.x - cd.x);
    }
    __syncthreads();

    // ---- Phase B: row-paired, v-folded column DFT ----
    // unit t: m = t>>2 (0..24), vb = t&3; lanes over v in [vb*32, vb*32+32)
    // computes G[32+m] and G[32-m] at v and 256-v, writes SG/DG (or G0 at m=0)
    for (int i = 0; i < 4; i++) {
        int t = warp + 32 * i;
        if (t >= 100) break;
        int m  = t >> 2;
        int vb = t & 3;
        int v  = (vb << 5) + lane;          // 0..127
        int r_up = 24 + m, r_dn = 24 - m;

        float2 w   = Wt[v];                 // angle v (mb=1)
        float2 rot = w;
        float A1u = 0.f, A2u = 0.f, A3u = 0.f, A4u = 0.f;
        float A1d = 0.f, A2d = 0.f, A3d = 0.f, A4d = 0.f;
        const float4* sup = SDB + r_up * 24;
        const float4* sdn = SDB + r_dn * 24;

        if (m == 0) {
            #pragma unroll 6
            for (int mb = 0; mb < 24; mb++) {
                float4 s = sup[mb];
                A1u = fmaf(w.x, s.x, A1u); A2u = fmaf(w.x, s.y, A2u);
                A3u = fmaf(w.y, s.z, A3u); A4u = fmaf(w.y, s.w, A4u);
                float nc = fmaf(w.x, rot.x, -(w.y * rot.y));
                float ns = fmaf(w.x, rot.y,  (w.y * rot.x));
                w.x = nc; w.y = ns;
            }
            float2 base = Cs[32 * 64 + 32];
            G0[v] = make_float2(base.x + A1u - A3u, base.y + A2u + A4u);
            G0[(256 - v) & 255] =
                    make_float2(base.x + A1u + A3u, base.y + A2u - A4u);
        } else {
            #pragma unroll 6
            for (int mb = 0; mb < 24; mb++) {
                float4 s = sup[mb];
                float4 d = sdn[mb];
                A1u = fmaf(w.x, s.x, A1u); A2u = fmaf(w.x, s.y, A2u);
                A3u = fmaf(w.y, s.z, A3u); A4u = fmaf(w.y, s.w, A4u);
                A1d = fmaf(w.x, d.x, A1d); A2d = fmaf(w.x, d.y, A2d);
                A3d = fmaf(w.y, d.z, A3d); A4d = fmaf(w.y, d.w, A4d);
                float nc = fmaf(w.x, rot.x, -(w.y * rot.y));
                float ns = fmaf(w.x, rot.y,  (w.y * rot.x));
                w.x = nc; w.y = ns;
            }
            float2 bu = Cs[(32 + m) * 64 + 32];
            float2 bd = Cs[(32 - m) * 64 + 32];
            float2 up_lo = make_float2(bu.x + A1u - A3u, bu.y + A2u + A4u);
            float2 up_hi = make_float2(bu.x + A1u + A3u, bu.y + A2u - A4u);
            float2 dn_lo = make_float2(bd.x + A1d - A3d, bd.y + A2d + A4d);
            float2 dn_hi = make_float2(bd.x + A1d + A3d, bd.y + A2d - A4d);
            int base = (m - 1) * 256;
            int vh = (256 - v) & 255;
            SG[base + v]  = make_float2(up_lo.x + dn_lo.x, up_lo.y + dn_lo.y);
            DG[base + v]  = make_float2(up_lo.y - dn_lo.y, up_lo.x - dn_lo.x);
            SG[base + vh] = make_float2(up_hi.x + dn_hi.x, up_hi.y + dn_hi.y);
            DG[base + vh] = make_float2(up_hi.y - dn_hi.y, up_hi.x - dn_hi.x);
        }
    }

    // ---- v = 128 column (sin = 0, cos = (-1)^mb) ----
    if (tid >= 896 && tid < 921) {
        int m = tid - 896;                  // 0..24
        float2 up = Cs[(32 + m) * 64 + 32];
        float2 dn = Cs[(32 - m) * 64 + 32];
        const float4* sup = SDB + (24 + m) * 24;
        const float4* sdn = SDB + (24 - m) * 24;
        float sgn = -1.f;
        #pragma unroll 6
        for (int mb = 0; mb < 24; mb++) {
            float4 su = sup[mb]; float4 sd = sdn[mb];
            up.x = fmaf(sgn, su.x, up.x); up.y = fmaf(sgn, su.y, up.y);
            dn.x = fmaf(sgn, sd.x, dn.x); dn.y = fmaf(sgn, sd.y, dn.y);
            sgn = -sgn;
        }
        if (m == 0) {
            G0[128] = up;
        } else {
            SG[(m - 1) * 256 + 128] = make_float2(up.x + dn.x, up.y + dn.y);
            DG[(m - 1) * 256 + 128] = make_float2(up.y - dn.y, up.x - dn.x);
        }
    }
    __syncthreads();

    // ---- Phase C: k-folded + u-folded row DFT with packed f32x2 FMA ----
    // unit t: ut = t>>3 (0..32) -> u0 = 4*ut (0..128); vb = t&7, v = vb*32+lane
    // per u in tile: outputs at u and 256-u (duplicated coverage for u>=129 ok)
    float lmax = 0.0f;
    const char* wp_base = (const char*)Wp;
    for (int i = 0; i < 9; i++) {
        int t = warp + 32 * i;
        if (t >= 264) break;
        int ut = t >> 3;
        int vb = t & 7;
        int v  = (vb << 5) + lane;
        int u0 = ut << 2;

        int o0 = (u0 + 0) * 16, o1 = (u0 + 1) * 16;
        int o2 = (u0 + 2) * 16, o3 = (u0 + 3) * 16;
        unsigned long long c0 = 0, s0 = 0, c1 = 0, s1 = 0;
        unsigned long long c2 = 0, s2 = 0, c3 = 0, s3 = 0;

        const char* sgp = (const char*)(SG + v);
        const char* dgp = (const char*)(DG + v);
        #pragma unroll 4
        for (int m = 1; m <= 24; m++) {
            unsigned long long gs = *(const unsigned long long*)sgp;
            unsigned long long gd = *(const unsigned long long*)dgp;
            sgp += 2048; dgp += 2048;
            ulonglong2 w0 = *(const ulonglong2*)(wp_base + o0);
            ulonglong2 w1 = *(const ulonglong2*)(wp_base + o1);
            ulonglong2 w2 = *(const ulonglong2*)(wp_base + o2);
            ulonglong2 w3 = *(const ulonglong2*)(wp_base + o3);
            FMA2(c0, w0.x, gs, c0); FMA2(s0, w0.y, gd, s0);
            FMA2(c1, w1.x, gs, c1); FMA2(s1, w1.y, gd, s1);
            FMA2(c2, w2.x, gs, c2); FMA2(s2, w2.y, gd, s2);
            FMA2(c3, w3.x, gs, c3); FMA2(s3, w3.y, gd, s3);
            o0 = (o0 + (u0 + 0) * 16) & 4095;
            o1 = (o1 + (u0 + 1) * 16) & 4095;
            o2 = (o2 + (u0 + 2) * 16) & 4095;
            o3 = (o3 + (u0 + 3) * 16) & 4095;
        }

        float2 g0 = G0[v];
        int t_col = (v + 32) & 255;
        bool tcol_ok = (t_col < 64);

        #pragma unroll
        for (int j = 0; j < 4; j++) {
            unsigned long long cj = (j == 0) ? c0 : (j == 1) ? c1 : (j == 2) ? c2 : c3;
            unsigned long long sj = (j == 0) ? s0 : (j == 1) ? s1 : (j == 2) ? s2 : s3;
            float2 ac = u2f2(cj);
            float2 as = u2f2(sj);
            float orx = g0.x + ac.x - as.x;   // out(u)
            float oix = g0.y + ac.y + as.y;
            float prx = g0.x + ac.x + as.x;   // out(256-u)
            float pix = g0.y + ac.y - as.y;
            float p2a = fmaf(orx, orx, oix * oix);
            float p2b = fmaf(prx, prx, pix * pix);
            lmax = fmaxf(lmax, fmaxf(p2a, p2b));
            if (tcol_ok) {
                int u  = u0 + j;
                int sa = (u + 32) & 255;
                if (sa < 64) crop[(sa << 6) + t_col] = p2a;
                int sb = (32 - u) & 255;
                if (sb < 64) crop[(sb << 6) + t_col] = p2b;
            }
        }
    }

    // ---- CTA max reduction ----
    #pragma unroll
    for (int o = 16; o > 0; o >>= 1)
        lmax = fmaxf(lmax, __shfl_xor_sync(0xFFFFFFFFu, lmax, o));
    if (lane == 0) red[warp] = lmax;
    __syncthreads();
    if (warp == 0) {
        float m = red[lane];
        #pragma unroll
        for (int o = 16; o > 0; o >>= 1)
            m = fmaxf(m, __shfl_xor_sync(0xFFFFFFFFu, m, o));
        if (lane == 0) red[0] = m;
    }
    __syncthreads();
    const float maxv = red[0];

    // ---- epilogue: img = (psf/max * A + bg) * (p > 0.5) -> g_tmp ----
    const float A    = Aa[img];
    const float bg   = Bg[img];
    const float mask = (P[img] > 0.5f) ? 1.0f : 0.0f;
    const float scale = (A / maxv) * mask;
    const float bgm   = bg * mask;
    #pragma unroll
    for (int k = 0; k < 4; k++) {
        int idx = tid + k * 1024;
        g_tmp[img * IMGPIX + idx] = fmaf(crop[idx], scale, bgm);
    }
}

__global__ void sum_kernel(float* __restrict__ out)
{
    int j = blockIdx.x * blockDim.x + threadIdx.x;
    if (j < 64 * IMGPIX) {
        int b = j >> 12, pix = j & 4095;
        const float* t = g_tmp + (size_t)(b * 4) * IMGPIX + pix;
        out[j] = (t[0] + t[IMGPIX]) + (t[2 * IMGPIX] + t[3 * IMGPIX]);
    }
}

extern "C" void kernel_launch(void* const* d_in, const int* in_sizes, int n_in,
                              void* d_out, int out_size)
{
    (void)in_sizes; (void)n_in; (void)out_size;
    cudaFuncSetAttribute(render_kernel,
                         cudaFuncAttributeMaxDynamicSharedMemorySize, SM_TOTAL);
    render_kernel<<<NIMG, 1024, SM_TOTAL>>>(
        (const float*)d_in[0], (const float*)d_in[1], (const float*)d_in[2],
        (const float*)d_in[3], (const float*)d_in[4], (const float*)d_in[5],
        (const float*)d_in[6]);
    sum_kernel<<<(64 * IMGPIX + 1023) / 1024, 1024>>>((float*)d_out);
}